// round 13
// baseline (speedup 1.0000x reference)
#include <cuda_runtime.h>
#include <cuda_fp16.h>
#include <cstdint>

#define NEGC (-10000000.0f)

// ---------------- device globals ----------------
__device__ __half g_G  [256 * 256];    // G = W1 @ W1^T (symmetric)
__device__ __half g_H1T[128 * 256];    // H1^T: [j][k] = (W1@W2top)[k][j]
__device__ __half g_H2T[128 * 256];    // H2^T
__device__ __half g_V  [4096 * 256];   // V = obs@G + vb
__device__ __half g_Ab [4096 * 256];   // abar = beta^T A
__device__ float  g_vb  [256];         // b1 @ W1^T
__device__ float  g_cvec[128];         // b1@(W2top+W2bot) + b2

// ---------------- helpers ----------------
__device__ __forceinline__ uint32_t smem_u32(const void* p) {
    uint32_t a;
    asm("{ .reg .u64 t; cvta.to.shared.u64 t, %1; cvt.u32.u64 %0, t; }" : "=r"(a) : "l"(p));
    return a;
}
__device__ __forceinline__ void ldsm4(uint32_t* r, uint32_t addr) {
    asm volatile("ldmatrix.sync.aligned.m8n8.x4.shared.b16 {%0,%1,%2,%3}, [%4];"
        : "=r"(r[0]), "=r"(r[1]), "=r"(r[2]), "=r"(r[3]) : "r"(addr));
}
__device__ __forceinline__ void mmah(uint32_t* d, const uint32_t* a, const uint32_t* b) {
    asm volatile("mma.sync.aligned.m16n8k16.row.col.f16.f16.f16.f16 "
        "{%0,%1}, {%2,%3,%4,%5}, {%6,%7}, {%0,%1};"
        : "+r"(d[0]), "+r"(d[1])
        : "r"(a[0]), "r"(a[1]), "r"(a[2]), "r"(a[3]), "r"(b[0]), "r"(b[1]));
}
__device__ __forceinline__ uint32_t sw_up(int u, int row) {
    return (uint32_t)((u & ~7) | ((u ^ row) & 7));
}
__device__ __forceinline__ uint32_t h2u(__half2 h) { return *(uint32_t*)&h; }

// f16 tile load (rows x U 16B-units/row) into swizzled smem
__device__ __forceinline__ void ld_tile(char* dst, const __half* src, int rows, int U,
                                        int srcStride, int t, int T) {
    int total = rows * U;
    for (int idx = t; idx < total; idx += T) {
        int row = idx / U, u = idx - row * U;
        uint4 v = *(const uint4*)(src + (size_t)row * srcStride + u * 8);
        *(uint4*)(dst + (size_t)row * U * 16 + sw_up(u, row) * 16) = v;
    }
}
// fp32 tile load + convert to f16 swizzled smem (coalesced)
__device__ __forceinline__ void ld_tile_cvt(char* dst, const float* src, int rows, int U,
                                            int srcStride, int t, int T) {
    int total = rows * U;
    for (int idx = t; idx < total; idx += T) {
        int row = idx / U, u = idx - row * U;
        const float* p = src + (size_t)row * srcStride + u * 8;
        float4 v0 = *(const float4*)p, v1 = *(const float4*)(p + 4);
        uint4 pk = make_uint4(h2u(__floats2half2_rn(v0.x, v0.y)),
                              h2u(__floats2half2_rn(v0.z, v0.w)),
                              h2u(__floats2half2_rn(v1.x, v1.y)),
                              h2u(__floats2half2_rn(v1.z, v1.w)));
        *(uint4*)(dst + (size_t)row * U * 16 + sw_up(u, row) * 16) = pk;
    }
}

// ---------------- prepW: G, H1T, H2T, vb, cvec (grid 34) ----------------
// bid 0..15 : G tile   (tm=bid&3 k-rows, tn=bid>>2 k-cols)
// bid 16..23: H1T tile (tm=(bid-16)&3 k-tile, tn=(bid-16)>>2 j-tile)
// bid 24..31: H2T tile
// bid 32: vb; bid 33: cvec
__global__ __launch_bounds__(256)
void prepW(const float* __restrict__ W1, const float* __restrict__ W2,
           const float* __restrict__ b1, const float* __restrict__ b2) {
    extern __shared__ char sm[];
    const uint32_t sb = smem_u32(sm);
    const int t = threadIdx.x, w = t >> 5, lane = t & 31;
    const int bid = blockIdx.x;

    if (bid == 32) {   // vb[k] = sum_n W1[k][n] b1[n]
        #pragma unroll
        for (int r = 0; r < 32; r++) {
            const int k = w * 32 + r;
            float s = 0.f;
            #pragma unroll
            for (int i = 0; i < 16; i++) s = fmaf(W1[k * 512 + lane + 32 * i], b1[lane + 32 * i], s);
            #pragma unroll
            for (int off = 16; off; off >>= 1) s += __shfl_xor_sync(~0u, s, off);
            if (lane == 0) g_vb[k] = s;
        }
        return;
    }
    if (bid == 33) {   // cvec[j] = b1@(W2top+W2bot)[.,j] + b2[j]
        #pragma unroll
        for (int r = 0; r < 16; r++) {
            const int j = w * 16 + r;
            float s = 0.f;
            #pragma unroll
            for (int i = 0; i < 16; i++) {
                const int n = lane + 32 * i;
                s = fmaf(b1[n], W2[n * 128 + j] + W2[(512 + n) * 128 + j], s);
            }
            #pragma unroll
            for (int off = 16; off; off >>= 1) s += __shfl_xor_sync(~0u, s, off);
            if (lane == 0) g_cvec[j] = s + b2[j];
        }
        return;
    }

    int tm, tn, mode;   // mode 0=G, 1=H1, 2=H2
    if (bid < 16)      { mode = 0; tm = bid & 3; tn = bid >> 2; }
    else if (bid < 24) { mode = 1; tm = (bid - 16) & 3; tn = (bid - 16) >> 2; }
    else               { mode = 2; tm = (bid - 24) & 3; tn = (bid - 24) >> 2; }
    const int w2off = (mode == 2) ? 512 : 0;

    const int wm = w & 3, wn = w >> 2;
    const int lrow = lane & 15, lkh = lane >> 4;
    const int g = lane >> 2, c = lane & 3;
    __half* stg = (__half*)(sm + 32768);   // staging [128 n][72 j] f16

    uint32_t acc[4][2] = {};
    for (int kc = 0; kc < 4; kc++) {
        __syncthreads();
        // A: W1 rows tm*64.., n-chunk kc*128 (fp32, coalesced, convert)
        ld_tile_cvt(sm, W1 + (size_t)(tm * 64) * 512 + kc * 128, 64, 16, 512, t, 256);
        if (mode == 0) {
            ld_tile_cvt(sm + 16384, W1 + (size_t)(tn * 64) * 512 + kc * 128, 64, 16, 512, t, 256);
        } else {
            // stage W2 block coalesced: stg[n][j] = f16(W2[(w2off+kc*128+n)*128 + tn*64 + j])
            for (int idx = t; idx < 128 * 16; idx += 256) {
                int n = idx >> 4, q = idx & 15;   // q: group of 4 j
                const float4 v = *(const float4*)(W2 + (size_t)(w2off + kc * 128 + n) * 128
                                                  + tn * 64 + q * 4);
                *(uint2*)(stg + n * 72 + q * 4) =
                    make_uint2(h2u(__floats2half2_rn(v.x, v.y)),
                               h2u(__floats2half2_rn(v.z, v.w)));
            }
            __syncthreads();
            // build B tile [64 j][128 n] from staging (row fastest -> conflict-free LDS)
            for (int idx = t; idx < 64 * 16; idx += 256) {
                int row = idx & 63, u = idx >> 6;
                u = (u + ((t & 256) ? 0 : 0));   // u spans 0..15 across iterations
                __half hh[8];
                #pragma unroll
                for (int e = 0; e < 8; e++) hh[e] = stg[(u * 8 + e) * 72 + row];
                uint4 pk = make_uint4(h2u(__halves2half2(hh[0], hh[1])),
                                      h2u(__halves2half2(hh[2], hh[3])),
                                      h2u(__halves2half2(hh[4], hh[5])),
                                      h2u(__halves2half2(hh[6], hh[7])));
                *(uint4*)(sm + 16384 + row * 256 + sw_up(u, row) * 16) = pk;
            }
        }
        __syncthreads();
        #pragma unroll
        for (int ks = 0; ks < 8; ks++) {
            const int u = ks * 2 + lkh;
            uint32_t af[4], bf[2][4];
            const int mrow = wm * 16 + lrow;
            ldsm4(af, sb + (uint32_t)(mrow * 256) + sw_up(u, mrow) * 16);
            #pragma unroll
            for (int nj = 0; nj < 2; nj++) {
                const int nb = wn * 32 + nj * 16 + lrow;
                ldsm4(bf[nj], sb + 16384u + (uint32_t)(nb * 256) + sw_up(u, nb) * 16);
            }
            #pragma unroll
            for (int nj = 0; nj < 2; nj++) {
                mmah(acc[nj * 2],     af, bf[nj]);
                mmah(acc[nj * 2 + 1], af, bf[nj] + 2);
            }
        }
    }
    #pragma unroll
    for (int ni = 0; ni < 4; ni++) {
        const int ncol = wn * 32 + ni * 8 + 2 * c;
        #pragma unroll
        for (int rr = 0; rr < 2; rr++) {
            const int r = wm * 16 + g + rr * 8;
            const __half2 hv = *(__half2*)&acc[ni][rr];
            if (mode == 0) {
                *(__half2*)(g_G + (size_t)(tm * 64 + r) * 256 + tn * 64 + ncol) = hv;
            } else {
                __half* dst = (mode == 1) ? g_H1T : g_H2T;
                dst[(size_t)(tn * 64 + ncol) * 256 + tm * 64 + r]     = __low2half(hv);
                dst[(size_t)(tn * 64 + ncol + 1) * 256 + tm * 64 + r] = __high2half(hv);
            }
        }
    }
}

// ---------------- kernelA: V[4096,256] = obs @ G + vb ----------------
// grid 128: bm=bid&63 (64 rows), bn=bid>>6 (2 x 128 cols). 256 thr.
__global__ __launch_bounds__(256, 2)
void kernelA(const float* __restrict__ obs) {
    extern __shared__ char sm[];
    const uint32_t sb = smem_u32(sm);
    float* vbs = (float*)(sm + 98304);
    const int t = threadIdx.x, w = t >> 5, lane = t & 31;
    const int bm = blockIdx.x & 63, bn = blockIdx.x >> 6;

    ld_tile_cvt(sm, obs + (size_t)(bm * 64) * 256, 64, 32, 256, t, 256);
    ld_tile(sm + 32768, g_G + (size_t)(bn * 128) * 256, 128, 32, 256, t, 256);
    if (t < 128) vbs[t] = g_vb[bn * 128 + t];
    __syncthreads();

    const int wm = w & 3, wn = w >> 2;
    const int lrow = lane & 15, lkh = lane >> 4;
    const int mrow = wm * 16 + lrow;
    const int g = lane >> 2, c = lane & 3;

    uint32_t acc[8][2] = {};
    #pragma unroll
    for (int ks = 0; ks < 16; ks++) {
        const int u = ks * 2 + lkh;
        uint32_t af[4], bf[4][4];
        ldsm4(af, sb + (uint32_t)(mrow * 512) + sw_up(u, mrow) * 16);
        #pragma unroll
        for (int nj = 0; nj < 4; nj++) {
            const int nb = wn * 64 + nj * 16 + lrow;
            ldsm4(bf[nj], sb + 32768u + (uint32_t)(nb * 512) + sw_up(u, nb) * 16);
        }
        #pragma unroll
        for (int nj = 0; nj < 4; nj++) {
            mmah(acc[nj * 2],     af, bf[nj]);
            mmah(acc[nj * 2 + 1], af, bf[nj] + 2);
        }
    }
    #pragma unroll
    for (int ni = 0; ni < 8; ni++) {
        const int ncol = wn * 64 + ni * 8 + 2 * c;
        #pragma unroll
        for (int rr = 0; rr < 2; rr++) {
            const int r = wm * 16 + g + rr * 8;
            float2 f = __half22float2(*(__half2*)&acc[ni][rr]);
            f.x += vbs[ncol]; f.y += vbs[ncol + 1];
            *(__half2*)(g_V + (size_t)(bm * 64 + r) * 256 + bn * 128 + ncol) =
                __floats2half2_rn(f.x, f.y);
        }
    }
}

// ---------------- attn: stream others; alpha=A.v fused into load; softmax; abar ----------------
__global__ __launch_bounds__(256, 6)
void attn_kernel(const float* __restrict__ others) {
    extern __shared__ char sm[];
    __half* A  = (__half*)sm;              // [64][264] f16 (pad 8)
    float* alp = (float*)(sm + 34304);     // [64]
    const int t = threadIdx.x, w = t >> 5, lane = t & 31;
    const int b = blockIdx.x;

    uint4 vv = *(const uint4*)(g_V + (size_t)b * 256 + lane * 8);
    const __half2* vh = (const __half2*)&vv;
    float2 vf[4];
    #pragma unroll
    for (int i = 0; i < 4; i++) vf[i] = __half22float2(vh[i]);

    const float* src = others + (size_t)b * 16384;
    #pragma unroll
    for (int r = 0; r < 8; r++) {
        const int row = w * 8 + r;
        const float* p = src + row * 256 + lane * 8;
        float4 x0 = *(const float4*)p;
        float4 x1 = *(const float4*)(p + 4);
        float s = x0.x * vf[0].x + x0.y * vf[0].y + x0.z * vf[1].x + x0.w * vf[1].y
                + x1.x * vf[2].x + x1.y * vf[2].y + x1.z * vf[3].x + x1.w * vf[3].y;
        uint4 pk;
        ((__half2*)&pk)[0] = __floats2half2_rn(x0.x, x0.y);
        ((__half2*)&pk)[1] = __floats2half2_rn(x0.z, x0.w);
        ((__half2*)&pk)[2] = __floats2half2_rn(x1.x, x1.y);
        ((__half2*)&pk)[3] = __floats2half2_rn(x1.z, x1.w);
        *(uint4*)((char*)A + row * 528 + lane * 16) = pk;
        #pragma unroll
        for (int off = 16; off; off >>= 1) s += __shfl_xor_sync(~0u, s, off);
        if (lane == 0) alp[row] = s * 0.04419417382415922f;
    }
    __syncthreads();
    if (w == 0) {  // softmax over 64
        float a0 = alp[lane], a1 = alp[lane + 32];
        float m = fmaxf(a0, a1);
        #pragma unroll
        for (int off = 16; off; off >>= 1) m = fmaxf(m, __shfl_xor_sync(~0u, m, off));
        float e0 = __expf(a0 - m), e1 = __expf(a1 - m);
        float s = e0 + e1;
        #pragma unroll
        for (int off = 16; off; off >>= 1) s += __shfl_xor_sync(~0u, s, off);
        float inv = 1.0f / s;
        alp[lane] = e0 * inv; alp[lane + 32] = e1 * inv;
    }
    __syncthreads();
    float acc = 0.f;
    #pragma unroll 16
    for (int n = 0; n < 64; n++)
        acc = fmaf(alp[n], __half2float(A[n * 264 + t]), acc);
    g_Ab[(size_t)b * 256 + t] = __float2half(acc);
}

// ---------------- kernelC: logits = [obs,Abar] @ [H1;H2]^T + cvec; softmax+mask ----------------
// grid 128 (32 rows each), 512 thr. smem: A 32K, B 128K, cvec; ls overlays A.
__global__ __launch_bounds__(512, 1)
void kernelC(const float* __restrict__ obs,
             const int* __restrict__ action_mask, float* __restrict__ out) {
    extern __shared__ char sm[];
    const uint32_t sb = smem_u32(sm);
    char* smB = sm + 32768;
    float* cvs = (float*)(sm + 163840);
    float* ls  = (float*)sm;               // [32][132] overlay after mainloop
    const int t = threadIdx.x, w = t >> 5, lane = t & 31;
    const int bm = blockIdx.x;

    // A: rows 32, units 0..31 = obs (fp32 cvt), 32..63 = Ab (f16)
    for (int idx = t; idx < 32 * 32; idx += 512) {
        int row = idx >> 5, u = idx & 31;
        const float* p = obs + (size_t)(bm * 32 + row) * 256 + u * 8;
        float4 v0 = *(const float4*)p, v1 = *(const float4*)(p + 4);
        uint4 pk = make_uint4(h2u(__floats2half2_rn(v0.x, v0.y)),
                              h2u(__floats2half2_rn(v0.z, v0.w)),
                              h2u(__floats2half2_rn(v1.x, v1.y)),
                              h2u(__floats2half2_rn(v1.z, v1.w)));
        *(uint4*)(sm + row * 1024 + sw_up(u, row) * 16) = pk;
        *(uint4*)(sm + row * 1024 + sw_up(32 + u, row) * 16) =
            *(const uint4*)(g_Ab + (size_t)(bm * 32 + row) * 256 + u * 8);
    }
    // B: rows j 0..127, units 0..31 = H1T, 32..63 = H2T
    for (int idx = t; idx < 128 * 32; idx += 512) {
        int j = idx >> 5, u = idx & 31;
        *(uint4*)(smB + j * 1024 + sw_up(u, j) * 16) =
            *(const uint4*)(g_H1T + (size_t)j * 256 + u * 8);
        *(uint4*)(smB + j * 1024 + sw_up(32 + u, j) * 16) =
            *(const uint4*)(g_H2T + (size_t)j * 256 + u * 8);
    }
    if (t < 128) cvs[t] = g_cvec[t];
    __syncthreads();

    const int wm = w & 1, wn = w >> 1;
    const int lrow = lane & 15, lkh = lane >> 4;
    const int mrow = wm * 16 + lrow;
    const int nb = wn * 16 + lrow;
    const int g = lane >> 2, c = lane & 3;

    uint32_t acc[2][2] = {};
    #pragma unroll
    for (int ks = 0; ks < 32; ks++) {
        const int u = ks * 2 + lkh;
        uint32_t af[4], bf[4];
        ldsm4(af, sb + (uint32_t)(mrow * 1024) + sw_up(u, mrow) * 16);
        ldsm4(bf, sb + 32768u + (uint32_t)(nb * 1024) + sw_up(u, nb) * 16);
        mmah(acc[0], af, bf); mmah(acc[1], af, bf + 2);
    }
    __syncthreads();   // A region becomes ls
    #pragma unroll
    for (int ni = 0; ni < 2; ni++) {
        const int col = wn * 16 + ni * 8 + 2 * c;
        #pragma unroll
        for (int rr = 0; rr < 2; rr++) {
            const int r = wm * 16 + g + rr * 8;
            float2 f = __half22float2(*(__half2*)&acc[ni][rr]);
            ls[r * 132 + col]     = f.x + cvs[col];
            ls[r * 132 + col + 1] = f.y + cvs[col + 1];
        }
    }
    __syncthreads();

    // softmax(128) + mask + write: warp w -> rows 2w, 2w+1
    #pragma unroll
    for (int rr = 0; rr < 2; rr++) {
        const int row = w * 2 + rr;
        float v0 = ls[row * 132 + lane],      v1 = ls[row * 132 + lane + 32];
        float v2 = ls[row * 132 + lane + 64], v3 = ls[row * 132 + lane + 96];
        float m = fmaxf(fmaxf(v0, v1), fmaxf(v2, v3));
        #pragma unroll
        for (int off = 16; off; off >>= 1) m = fmaxf(m, __shfl_xor_sync(~0u, m, off));
        float e0 = __expf(v0 - m), e1 = __expf(v1 - m);
        float e2 = __expf(v2 - m), e3 = __expf(v3 - m);
        float s = e0 + e1 + e2 + e3;
        #pragma unroll
        for (int off = 16; off; off >>= 1) s += __shfl_xor_sync(~0u, s, off);
        const float inv = 1.0f / s;
        const size_t gb = (size_t)(bm * 32 + row);
        const int* mk = action_mask + gb * 128;
        float* op = out + gb * 128;
        op[lane]      = e0 * inv + NEGC * (1.0f - (float)mk[lane]);
        op[lane + 32] = e1 * inv + NEGC * (1.0f - (float)mk[lane + 32]);
        op[lane + 64] = e2 * inv + NEGC * (1.0f - (float)mk[lane + 64]);
        op[lane + 96] = e3 * inv + NEGC * (1.0f - (float)mk[lane + 96]);
    }
}

extern "C" void kernel_launch(void* const* d_in, const int* in_sizes, int n_in,
                              void* d_out, int out_size)
{
    const float* obs_x       = (const float*)d_in[0];
    const float* others      = (const float*)d_in[1];
    const int*   action_mask = (const int*)  d_in[2];
    const float* W1          = (const float*)d_in[3];
    const float* b1          = (const float*)d_in[4];
    const float* W2          = (const float*)d_in[5];
    const float* b2          = (const float*)d_in[6];
    // d_in[7..10] = W3,b3,W4,b4: dead in reference forward(), unused.

    cudaFuncSetAttribute(prepW,       cudaFuncAttributeMaxDynamicSharedMemorySize, 51200);
    cudaFuncSetAttribute(kernelA,     cudaFuncAttributeMaxDynamicSharedMemorySize, 98816);
    cudaFuncSetAttribute(attn_kernel, cudaFuncAttributeMaxDynamicSharedMemorySize, 34816);
    cudaFuncSetAttribute(kernelC,     cudaFuncAttributeMaxDynamicSharedMemorySize, 164352);

    prepW<<<34, 256, 51200>>>(W1, W2, b1, b2);
    kernelA<<<128, 256, 98816>>>(obs_x);
    attn_kernel<<<4096, 256, 34816>>>(others);
    kernelC<<<128, 512, 164352>>>(obs_x, action_mask, (float*)d_out);
}

// round 14
// speedup vs baseline: 1.0664x; 1.0664x over previous
#include <cuda_runtime.h>
#include <cuda_fp16.h>
#include <cstdint>

#define NEGC (-10000000.0f)

// ---------------- device globals ----------------
__device__ __half g_G  [256 * 256];    // G = W1 @ W1^T (symmetric)
__device__ __half g_H1T[128 * 256];    // H1^T: [j][k] = (W1@W2top)[k][j]
__device__ __half g_H2T[128 * 256];    // H2^T
__device__ __half g_V  [4096 * 256];   // V = obs@G + vb
__device__ __half g_Ab [4096 * 256];   // abar = beta^T A
__device__ float  g_vb  [256];         // b1 @ W1^T
__device__ float  g_cvec[128];         // b1@(W2top+W2bot) + b2

// ---------------- helpers ----------------
__device__ __forceinline__ uint32_t smem_u32(const void* p) {
    uint32_t a;
    asm("{ .reg .u64 t; cvta.to.shared.u64 t, %1; cvt.u32.u64 %0, t; }" : "=r"(a) : "l"(p));
    return a;
}
__device__ __forceinline__ void ldsm4(uint32_t* r, uint32_t addr) {
    asm volatile("ldmatrix.sync.aligned.m8n8.x4.shared.b16 {%0,%1,%2,%3}, [%4];"
        : "=r"(r[0]), "=r"(r[1]), "=r"(r[2]), "=r"(r[3]) : "r"(addr));
}
__device__ __forceinline__ void mmah(uint32_t* d, const uint32_t* a, const uint32_t* b) {
    asm volatile("mma.sync.aligned.m16n8k16.row.col.f16.f16.f16.f16 "
        "{%0,%1}, {%2,%3,%4,%5}, {%6,%7}, {%0,%1};"
        : "+r"(d[0]), "+r"(d[1])
        : "r"(a[0]), "r"(a[1]), "r"(a[2]), "r"(a[3]), "r"(b[0]), "r"(b[1]));
}
__device__ __forceinline__ uint32_t sw_up(int u, int row) {
    return (uint32_t)((u & ~7) | ((u ^ row) & 7));
}
__device__ __forceinline__ uint32_t h2u(__half2 h) { return *(uint32_t*)&h; }

// f16 tile load (rows x U 16B-units/row) into swizzled smem
__device__ __forceinline__ void ld_tile(char* dst, const __half* src, int rows, int U,
                                        int srcStride, int t, int T) {
    int total = rows * U;
    for (int idx = t; idx < total; idx += T) {
        int row = idx / U, u = idx - row * U;
        uint4 v = *(const uint4*)(src + (size_t)row * srcStride + u * 8);
        *(uint4*)(dst + (size_t)row * U * 16 + sw_up(u, row) * 16) = v;
    }
}
// fp32 tile load + convert to f16 swizzled smem (coalesced)
__device__ __forceinline__ void ld_tile_cvt(char* dst, const float* src, int rows, int U,
                                            int srcStride, int t, int T) {
    int total = rows * U;
    for (int idx = t; idx < total; idx += T) {
        int row = idx / U, u = idx - row * U;
        const float* p = src + (size_t)row * srcStride + u * 8;
        float4 v0 = *(const float4*)p, v1 = *(const float4*)(p + 4);
        uint4 pk = make_uint4(h2u(__floats2half2_rn(v0.x, v0.y)),
                              h2u(__floats2half2_rn(v0.z, v0.w)),
                              h2u(__floats2half2_rn(v1.x, v1.y)),
                              h2u(__floats2half2_rn(v1.z, v1.w)));
        *(uint4*)(dst + (size_t)row * U * 16 + sw_up(u, row) * 16) = pk;
    }
}

// ---------------- prepW: G, H1T, H2T, vb, cvec (grid 34) ----------------
// bid 0..15 : G tile   (tm=bid&3 k-rows, tn=bid>>2 k-cols)
// bid 16..23: H1T tile (tm=(bid-16)&3 k-tile, tn=(bid-16)>>2 j-tile)
// bid 24..31: H2T tile
// bid 32: vb; bid 33: cvec
__global__ __launch_bounds__(256)
void prepW(const float* __restrict__ W1, const float* __restrict__ W2,
           const float* __restrict__ b1, const float* __restrict__ b2) {
    extern __shared__ char sm[];
    const uint32_t sb = smem_u32(sm);
    const int t = threadIdx.x, w = t >> 5, lane = t & 31;
    const int bid = blockIdx.x;

    if (bid == 32) {   // vb[k] = sum_n W1[k][n] b1[n]
        #pragma unroll
        for (int r = 0; r < 32; r++) {
            const int k = w * 32 + r;
            float s = 0.f;
            #pragma unroll
            for (int i = 0; i < 16; i++) s = fmaf(W1[k * 512 + lane + 32 * i], b1[lane + 32 * i], s);
            #pragma unroll
            for (int off = 16; off; off >>= 1) s += __shfl_xor_sync(~0u, s, off);
            if (lane == 0) g_vb[k] = s;
        }
        return;
    }
    if (bid == 33) {   // cvec[j] = b1@(W2top+W2bot)[.,j] + b2[j]
        #pragma unroll
        for (int r = 0; r < 16; r++) {
            const int j = w * 16 + r;
            float s = 0.f;
            #pragma unroll
            for (int i = 0; i < 16; i++) {
                const int n = lane + 32 * i;
                s = fmaf(b1[n], W2[n * 128 + j] + W2[(512 + n) * 128 + j], s);
            }
            #pragma unroll
            for (int off = 16; off; off >>= 1) s += __shfl_xor_sync(~0u, s, off);
            if (lane == 0) g_cvec[j] = s + b2[j];
        }
        return;
    }

    int tm, tn, mode;   // mode 0=G, 1=H1, 2=H2
    if (bid < 16)      { mode = 0; tm = bid & 3; tn = bid >> 2; }
    else if (bid < 24) { mode = 1; tm = (bid - 16) & 3; tn = (bid - 16) >> 2; }
    else               { mode = 2; tm = (bid - 24) & 3; tn = (bid - 24) >> 2; }
    const int w2off = (mode == 2) ? 512 : 0;

    const int wm = w & 3, wn = w >> 2;
    const int lrow = lane & 15, lkh = lane >> 4;
    const int g = lane >> 2, c = lane & 3;
    __half* stg = (__half*)(sm + 32768);   // staging [128 n][72 j] f16

    uint32_t acc[4][2] = {};
    for (int kc = 0; kc < 4; kc++) {
        __syncthreads();
        // A: W1 rows tm*64.., n-chunk kc*128 (fp32, coalesced, convert)
        ld_tile_cvt(sm, W1 + (size_t)(tm * 64) * 512 + kc * 128, 64, 16, 512, t, 256);
        if (mode == 0) {
            ld_tile_cvt(sm + 16384, W1 + (size_t)(tn * 64) * 512 + kc * 128, 64, 16, 512, t, 256);
        } else {
            // stage W2 block coalesced: stg[n][j] = f16(W2[(w2off+kc*128+n)*128 + tn*64 + j])
            for (int idx = t; idx < 128 * 16; idx += 256) {
                int n = idx >> 4, q = idx & 15;   // q: group of 4 j
                const float4 v = *(const float4*)(W2 + (size_t)(w2off + kc * 128 + n) * 128
                                                  + tn * 64 + q * 4);
                *(uint2*)(stg + n * 72 + q * 4) =
                    make_uint2(h2u(__floats2half2_rn(v.x, v.y)),
                               h2u(__floats2half2_rn(v.z, v.w)));
            }
            __syncthreads();
            // build B tile [64 j][128 n] from staging (row fastest -> conflict-free LDS)
            for (int idx = t; idx < 64 * 16; idx += 256) {
                int row = idx & 63, u = idx >> 6;
                __half hh[8];
                #pragma unroll
                for (int e = 0; e < 8; e++) hh[e] = stg[(u * 8 + e) * 72 + row];
                uint4 pk = make_uint4(h2u(__halves2half2(hh[0], hh[1])),
                                      h2u(__halves2half2(hh[2], hh[3])),
                                      h2u(__halves2half2(hh[4], hh[5])),
                                      h2u(__halves2half2(hh[6], hh[7])));
                *(uint4*)(sm + 16384 + row * 256 + sw_up(u, row) * 16) = pk;
            }
        }
        __syncthreads();
        #pragma unroll
        for (int ks = 0; ks < 8; ks++) {
            const int u = ks * 2 + lkh;
            uint32_t af[4], bf[2][4];
            const int mrow = wm * 16 + lrow;
            ldsm4(af, sb + (uint32_t)(mrow * 256) + sw_up(u, mrow) * 16);
            #pragma unroll
            for (int nj = 0; nj < 2; nj++) {
                const int nb = wn * 32 + nj * 16 + lrow;
                ldsm4(bf[nj], sb + 16384u + (uint32_t)(nb * 256) + sw_up(u, nb) * 16);
            }
            #pragma unroll
            for (int nj = 0; nj < 2; nj++) {
                mmah(acc[nj * 2],     af, bf[nj]);
                mmah(acc[nj * 2 + 1], af, bf[nj] + 2);
            }
        }
    }
    #pragma unroll
    for (int ni = 0; ni < 4; ni++) {
        const int ncol = wn * 32 + ni * 8 + 2 * c;
        #pragma unroll
        for (int rr = 0; rr < 2; rr++) {
            const int r = wm * 16 + g + rr * 8;
            const __half2 hv = *(__half2*)&acc[ni][rr];
            if (mode == 0) {
                *(__half2*)(g_G + (size_t)(tm * 64 + r) * 256 + tn * 64 + ncol) = hv;
            } else {
                __half* dst = (mode == 1) ? g_H1T : g_H2T;
                dst[(size_t)(tn * 64 + ncol) * 256 + tm * 64 + r]     = __low2half(hv);
                dst[(size_t)(tn * 64 + ncol + 1) * 256 + tm * 64 + r] = __high2half(hv);
            }
        }
    }
}

// ---------------- kernelA: V[4096,256] = obs @ G + vb ----------------
// grid 128: bm=bid&63 (64 rows), bn=bid>>6 (2 x 128 cols). 256 thr.
__global__ __launch_bounds__(256, 2)
void kernelA(const float* __restrict__ obs) {
    extern __shared__ char sm[];
    const uint32_t sb = smem_u32(sm);
    float* vbs = (float*)(sm + 98304);
    const int t = threadIdx.x, w = t >> 5, lane = t & 31;
    const int bm = blockIdx.x & 63, bn = blockIdx.x >> 6;

    ld_tile_cvt(sm, obs + (size_t)(bm * 64) * 256, 64, 32, 256, t, 256);
    ld_tile(sm + 32768, g_G + (size_t)(bn * 128) * 256, 128, 32, 256, t, 256);
    if (t < 128) vbs[t] = g_vb[bn * 128 + t];
    __syncthreads();

    const int wm = w & 3, wn = w >> 2;
    const int lrow = lane & 15, lkh = lane >> 4;
    const int mrow = wm * 16 + lrow;
    const int g = lane >> 2, c = lane & 3;

    uint32_t acc[8][2] = {};
    #pragma unroll
    for (int ks = 0; ks < 16; ks++) {
        const int u = ks * 2 + lkh;
        uint32_t af[4], bf[4][4];
        ldsm4(af, sb + (uint32_t)(mrow * 512) + sw_up(u, mrow) * 16);
        #pragma unroll
        for (int nj = 0; nj < 4; nj++) {
            const int nb = wn * 64 + nj * 16 + lrow;
            ldsm4(bf[nj], sb + 32768u + (uint32_t)(nb * 512) + sw_up(u, nb) * 16);
        }
        #pragma unroll
        for (int nj = 0; nj < 4; nj++) {
            mmah(acc[nj * 2],     af, bf[nj]);
            mmah(acc[nj * 2 + 1], af, bf[nj] + 2);
        }
    }
    #pragma unroll
    for (int ni = 0; ni < 8; ni++) {
        const int ncol = wn * 64 + ni * 8 + 2 * c;
        #pragma unroll
        for (int rr = 0; rr < 2; rr++) {
            const int r = wm * 16 + g + rr * 8;
            float2 f = __half22float2(*(__half2*)&acc[ni][rr]);
            f.x += vbs[ncol]; f.y += vbs[ncol + 1];
            *(__half2*)(g_V + (size_t)(bm * 64 + r) * 256 + bn * 128 + ncol) =
                __floats2half2_rn(f.x, f.y);
        }
    }
}

// ---------------- attn: stream others; alpha=A.v fused into load; softmax; abar ----------------
__global__ __launch_bounds__(256, 4)
void attn_kernel(const float* __restrict__ others) {
    extern __shared__ char sm[];
    __half* A  = (__half*)sm;              // [64][264] f16 (pad 8)
    float* alp = (float*)(sm + 34304);     // [64]
    const int t = threadIdx.x, w = t >> 5, lane = t & 31;
    const int b = blockIdx.x;

    uint4 vv = *(const uint4*)(g_V + (size_t)b * 256 + lane * 8);
    const __half2* vh = (const __half2*)&vv;
    float2 vf[4];
    #pragma unroll
    for (int i = 0; i < 4; i++) vf[i] = __half22float2(vh[i]);

    const float* src = others + (size_t)b * 16384;
    #pragma unroll
    for (int r = 0; r < 8; r++) {
        const int row = w * 8 + r;
        const float* p = src + row * 256 + lane * 8;
        float4 x0 = *(const float4*)p;
        float4 x1 = *(const float4*)(p + 4);
        float s = x0.x * vf[0].x + x0.y * vf[0].y + x0.z * vf[1].x + x0.w * vf[1].y
                + x1.x * vf[2].x + x1.y * vf[2].y + x1.z * vf[3].x + x1.w * vf[3].y;
        uint4 pk;
        ((__half2*)&pk)[0] = __floats2half2_rn(x0.x, x0.y);
        ((__half2*)&pk)[1] = __floats2half2_rn(x0.z, x0.w);
        ((__half2*)&pk)[2] = __floats2half2_rn(x1.x, x1.y);
        ((__half2*)&pk)[3] = __floats2half2_rn(x1.z, x1.w);
        *(uint4*)((char*)A + row * 528 + lane * 16) = pk;
        #pragma unroll
        for (int off = 16; off; off >>= 1) s += __shfl_xor_sync(~0u, s, off);
        if (lane == 0) alp[row] = s * 0.04419417382415922f;
    }
    __syncthreads();
    if (w == 0) {  // softmax over 64
        float a0 = alp[lane], a1 = alp[lane + 32];
        float m = fmaxf(a0, a1);
        #pragma unroll
        for (int off = 16; off; off >>= 1) m = fmaxf(m, __shfl_xor_sync(~0u, m, off));
        float e0 = __expf(a0 - m), e1 = __expf(a1 - m);
        float s = e0 + e1;
        #pragma unroll
        for (int off = 16; off; off >>= 1) s += __shfl_xor_sync(~0u, s, off);
        float inv = 1.0f / s;
        alp[lane] = e0 * inv; alp[lane + 32] = e1 * inv;
    }
    __syncthreads();
    float acc = 0.f;
    #pragma unroll 16
    for (int n = 0; n < 64; n++)
        acc = fmaf(alp[n], __half2float(A[n * 264 + t]), acc);
    g_Ab[(size_t)b * 256 + t] = __float2half(acc);
}

// ---------------- kernelC: logits = [obs,Abar] @ [H1;H2]^T + cvec; softmax+mask ----------------
// grid 128 (32 rows each), 512 thr. smem: A 32K, B 128K, cvec; ls overlays A.
__global__ __launch_bounds__(512, 1)
void kernelC(const float* __restrict__ obs,
             const int* __restrict__ action_mask, float* __restrict__ out) {
    extern __shared__ char sm[];
    const uint32_t sb = smem_u32(sm);
    char* smB = sm + 32768;
    float* cvs = (float*)(sm + 163840);
    float* ls  = (float*)sm;               // [32][132] overlay after mainloop
    const int t = threadIdx.x, w = t >> 5, lane = t & 31;
    const int bm = blockIdx.x;

    // A: rows 32, units 0..31 = obs (fp32 cvt), 32..63 = Ab (f16)
    for (int idx = t; idx < 32 * 32; idx += 512) {
        int row = idx >> 5, u = idx & 31;
        const float* p = obs + (size_t)(bm * 32 + row) * 256 + u * 8;
        float4 v0 = *(const float4*)p, v1 = *(const float4*)(p + 4);
        uint4 pk = make_uint4(h2u(__floats2half2_rn(v0.x, v0.y)),
                              h2u(__floats2half2_rn(v0.z, v0.w)),
                              h2u(__floats2half2_rn(v1.x, v1.y)),
                              h2u(__floats2half2_rn(v1.w, v1.w)));
        // note: last pair must be (v1.z, v1.w); fix below
        pk.w = h2u(__floats2half2_rn(v1.z, v1.w));
        *(uint4*)(sm + row * 1024 + sw_up(u, row) * 16) = pk;
        *(uint4*)(sm + row * 1024 + sw_up(32 + u, row) * 16) =
            *(const uint4*)(g_Ab + (size_t)(bm * 32 + row) * 256 + u * 8);
    }
    // B: rows j 0..127, units 0..31 = H1T, 32..63 = H2T
    for (int idx = t; idx < 128 * 32; idx += 512) {
        int j = idx >> 5, u = idx & 31;
        *(uint4*)(smB + j * 1024 + sw_up(u, j) * 16) =
            *(const uint4*)(g_H1T + (size_t)j * 256 + u * 8);
        *(uint4*)(smB + j * 1024 + sw_up(32 + u, j) * 16) =
            *(const uint4*)(g_H2T + (size_t)j * 256 + u * 8);
    }
    if (t < 128) cvs[t] = g_cvec[t];
    __syncthreads();

    const int wm = w & 1, wn = w >> 1;
    const int lrow = lane & 15, lkh = lane >> 4;
    const int mrow = wm * 16 + lrow;
    const int nb = wn * 16 + lrow;
    const int g = lane >> 2, c = lane & 3;

    uint32_t acc[2][2] = {};
    #pragma unroll
    for (int ks = 0; ks < 32; ks++) {
        const int u = ks * 2 + lkh;
        uint32_t af[4], bf[4];
        ldsm4(af, sb + (uint32_t)(mrow * 1024) + sw_up(u, mrow) * 16);
        ldsm4(bf, sb + 32768u + (uint32_t)(nb * 1024) + sw_up(u, nb) * 16);
        mmah(acc[0], af, bf); mmah(acc[1], af, bf + 2);
    }
    __syncthreads();   // A region becomes ls
    #pragma unroll
    for (int ni = 0; ni < 2; ni++) {
        const int col = wn * 16 + ni * 8 + 2 * c;
        #pragma unroll
        for (int rr = 0; rr < 2; rr++) {
            const int r = wm * 16 + g + rr * 8;
            float2 f = __half22float2(*(__half2*)&acc[ni][rr]);
            ls[r * 132 + col]     = f.x + cvs[col];
            ls[r * 132 + col + 1] = f.y + cvs[col + 1];
        }
    }
    __syncthreads();

    // softmax(128) + mask + write: warp w -> rows 2w, 2w+1
    #pragma unroll
    for (int rr = 0; rr < 2; rr++) {
        const int row = w * 2 + rr;
        float v0 = ls[row * 132 + lane],      v1 = ls[row * 132 + lane + 32];
        float v2 = ls[row * 132 + lane + 64], v3 = ls[row * 132 + lane + 96];
        float m = fmaxf(fmaxf(v0, v1), fmaxf(v2, v3));
        #pragma unroll
        for (int off = 16; off; off >>= 1) m = fmaxf(m, __shfl_xor_sync(~0u, m, off));
        float e0 = __expf(v0 - m), e1 = __expf(v1 - m);
        float e2 = __expf(v2 - m), e3 = __expf(v3 - m);
        float s = e0 + e1 + e2 + e3;
        #pragma unroll
        for (int off = 16; off; off >>= 1) s += __shfl_xor_sync(~0u, s, off);
        const float inv = 1.0f / s;
        const size_t gb = (size_t)(bm * 32 + row);
        const int* mk = action_mask + gb * 128;
        float* op = out + gb * 128;
        op[lane]      = e0 * inv + NEGC * (1.0f - (float)mk[lane]);
        op[lane + 32] = e1 * inv + NEGC * (1.0f - (float)mk[lane + 32]);
        op[lane + 64] = e2 * inv + NEGC * (1.0f - (float)mk[lane + 64]);
        op[lane + 96] = e3 * inv + NEGC * (1.0f - (float)mk[lane + 96]);
    }
}

extern "C" void kernel_launch(void* const* d_in, const int* in_sizes, int n_in,
                              void* d_out, int out_size)
{
    const float* obs_x       = (const float*)d_in[0];
    const float* others      = (const float*)d_in[1];
    const int*   action_mask = (const int*)  d_in[2];
    const float* W1          = (const float*)d_in[3];
    const float* b1          = (const float*)d_in[4];
    const float* W2          = (const float*)d_in[5];
    const float* b2          = (const float*)d_in[6];
    // d_in[7..10] = W3,b3,W4,b4: dead in reference forward(), unused.

    cudaFuncSetAttribute(prepW,       cudaFuncAttributeMaxDynamicSharedMemorySize, 51200);
    cudaFuncSetAttribute(kernelA,     cudaFuncAttributeMaxDynamicSharedMemorySize, 98816);
    cudaFuncSetAttribute(attn_kernel, cudaFuncAttributeMaxDynamicSharedMemorySize, 34816);
    cudaFuncSetAttribute(kernelC,     cudaFuncAttributeMaxDynamicSharedMemorySize, 164352);

    prepW<<<34, 256, 51200>>>(W1, W2, b1, b2);
    kernelA<<<128, 256, 98816>>>(obs_x);
    attn_kernel<<<4096, 256, 34816>>>(others);
    kernelC<<<128, 512, 164352>>>(obs_x, action_mask, (float*)d_out);
}

// round 15
// speedup vs baseline: 1.5577x; 1.4607x over previous
#include <cuda_runtime.h>
#include <cuda_fp16.h>
#include <cstdint>

#define NEGC (-10000000.0f)

// ---------------- device globals ----------------
__device__ __half g_W1T[512 * 256];    // W1T[n][k] = W1[k][n]
__device__ __half g_W1R[256 * 512];    // W1 row-major f16
__device__ __half g_W2T[128 * 1024];   // W2T[j][i] = W2[i][j]
__device__ __half g_X [4096 * 512];    // X = obs @ W1 + b1
__device__ __half g_V [4096 * 256];    // V = X @ W1^T  (v_b = W1 x_b)
__device__ __half g_Ab[4096 * 256];    // abar = beta^T A

// ---------------- helpers ----------------
__device__ __forceinline__ uint32_t smem_u32(const void* p) {
    uint32_t a;
    asm("{ .reg .u64 t; cvta.to.shared.u64 t, %1; cvt.u32.u64 %0, t; }" : "=r"(a) : "l"(p));
    return a;
}
__device__ __forceinline__ void ldsm4(uint32_t* r, uint32_t addr) {
    asm volatile("ldmatrix.sync.aligned.m8n8.x4.shared.b16 {%0,%1,%2,%3}, [%4];"
        : "=r"(r[0]), "=r"(r[1]), "=r"(r[2]), "=r"(r[3]) : "r"(addr));
}
__device__ __forceinline__ void mmah(uint32_t* d, const uint32_t* a, const uint32_t* b) {
    asm volatile("mma.sync.aligned.m16n8k16.row.col.f16.f16.f16.f16 "
        "{%0,%1}, {%2,%3,%4,%5}, {%6,%7}, {%0,%1};"
        : "+r"(d[0]), "+r"(d[1])
        : "r"(a[0]), "r"(a[1]), "r"(a[2]), "r"(a[3]), "r"(b[0]), "r"(b[1]));
}
__device__ __forceinline__ uint32_t sw_up(int u, int row) {
    return (uint32_t)((u & ~7) | ((u ^ row) & 7));
}
// load f16 tile (rows x U 16B-units per row) into swizzled smem
__device__ __forceinline__ void ld_tile(char* dst, const __half* src, int rows, int U,
                                        int srcStride, int t, int T) {
    int total = rows * U;
    for (int idx = t; idx < total; idx += T) {
        int row = idx / U, u = idx - row * U;
        uint4 v = *(const uint4*)(src + (size_t)row * srcStride + u * 8);
        *(uint4*)(dst + (size_t)row * U * 16 + sw_up(u, row) * 16) = v;
    }
}
__device__ __forceinline__ uint32_t h2u(__half2 h) { return *(uint32_t*)&h; }

// ---------------- prep1 ----------------
__global__ void prep1(const float* __restrict__ W1, const float* __restrict__ W2,
                      const float* __restrict__ obs,
                      const float* __restrict__ b1, const float* __restrict__ b2) {
    int i = blockIdx.x * blockDim.x + threadIdx.x;
    int stride = gridDim.x * blockDim.x;
    for (int idx = i; idx < 512 * 256; idx += stride) {
        int n = idx >> 8, k = idx & 255;
        g_W1T[idx] = __float2half(W1[k * 512 + n]);
    }
    for (int idx = i; idx < 256 * 512; idx += stride)
        g_W1R[idx] = __float2half(W1[idx]);
    for (int idx = i; idx < 128 * 1024; idx += stride) {
        int j = idx >> 10, k = idx & 1023;
        g_W2T[idx] = __float2half(W2[k * 128 + j]);
    }
}

// ---------------- GEMM1: X[4096,512] = obs[4096,256] @ W1 + b1 ----------------
__global__ __launch_bounds__(512, 2)
void gemm1(const float* __restrict__ obs, const float* __restrict__ b1g) {
    extern __shared__ char sm[];
    const uint32_t sb = smem_u32(sm);
    char* smA = sm;             // 64 x 32u
    char* smB = sm + 32768;     // 128 x 32u
    __half* b1s = (__half*)(sm + 98304);
    const int t = threadIdx.x, w = t >> 5, lane = t & 31;
    const int bm = blockIdx.x & 63, bn = blockIdx.x >> 6;

    #pragma unroll
    for (int it = 0; it < 4; it++) {
        int idx = it * 512 + t;
        int row = idx >> 5, u = idx & 31;
        const float* src = obs + (size_t)(bm * 64 + row) * 256 + u * 8;
        float4 v0 = *(const float4*)src, v1 = *(const float4*)(src + 4);
        uint4 pk = make_uint4(h2u(__floats2half2_rn(v0.x, v0.y)), h2u(__floats2half2_rn(v0.z, v0.w)),
                              h2u(__floats2half2_rn(v1.x, v1.y)), h2u(__floats2half2_rn(v1.z, v1.w)));
        *(uint4*)(smA + row * 512 + sw_up(u, row) * 16) = pk;
    }
    ld_tile(smB, g_W1T + (size_t)(bn * 128) * 256, 128, 32, 256, t, 512);
    if (t < 128) b1s[t] = __float2half(b1g[bn * 128 + t]);
    __syncthreads();

    const int wm = w & 3, wn = w >> 2;
    const int lrow = lane & 15, lkh = lane >> 4;
    const int mrow = wm * 16 + lrow;
    const int nb0 = wn * 32 + lrow, nb1 = nb0 + 16;
    const int g = lane >> 2, c = lane & 3;

    uint32_t acc[4][2] = {};
    #pragma unroll
    for (int ks = 0; ks < 16; ks++) {
        const int u = ks * 2 + lkh;
        uint32_t af[4], bf0[4], bf1[4];
        ldsm4(af,  sb + (uint32_t)(mrow * 512) + sw_up(u, mrow) * 16);
        ldsm4(bf0, sb + 32768u + (uint32_t)(nb0 * 512) + sw_up(u, nb0) * 16);
        ldsm4(bf1, sb + 32768u + (uint32_t)(nb1 * 512) + sw_up(u, nb1) * 16);
        mmah(acc[0], af, bf0); mmah(acc[1], af, bf0 + 2);
        mmah(acc[2], af, bf1); mmah(acc[3], af, bf1 + 2);
    }
    #pragma unroll
    for (int ni = 0; ni < 4; ni++) {
        const int ncol = wn * 32 + ni * 8 + 2 * c;
        const __half2 bias = *(__half2*)&b1s[ncol];
        const int r0 = wm * 16 + g;
        __half* dst = g_X + (size_t)(bm * 64 + r0) * 512 + bn * 128 + ncol;
        *(__half2*)dst            = __hadd2(*(__half2*)&acc[ni][0], bias);
        *(__half2*)(dst + 8*512)  = __hadd2(*(__half2*)&acc[ni][1], bias);
    }
}

// ---------------- GEMM2: V[4096,256] = X[4096,512] @ W1R^T ----------------
__global__ __launch_bounds__(512, 1)
void gemm2() {
    extern __shared__ char sm[];
    const uint32_t sb = smem_u32(sm);
    const int t = threadIdx.x, w = t >> 5, lane = t & 31;
    const int bm = blockIdx.x & 63, bn = blockIdx.x >> 6;

    ld_tile(sm,          g_X   + (size_t)(bm * 64) * 512, 64, 64, 512, t, 512);
    ld_tile(sm + 65536,  g_W1R + (size_t)(bn * 64) * 512, 64, 64, 512, t, 512);
    __syncthreads();

    const int wm = w & 3, wn = w >> 2;
    const int lrow = lane & 15, lkh = lane >> 4;
    const int mrow = wm * 16 + lrow;
    const int nb = wn * 16 + lrow;
    const int g = lane >> 2, c = lane & 3;

    uint32_t acc[2][2] = {};
    #pragma unroll
    for (int ks = 0; ks < 32; ks++) {
        const int u = ks * 2 + lkh;
        uint32_t af[4], bf[4];
        ldsm4(af, sb + (uint32_t)(mrow * 1024) + sw_up(u, mrow) * 16);
        ldsm4(bf, sb + 65536u + (uint32_t)(nb * 1024) + sw_up(u, nb) * 16);
        mmah(acc[0], af, bf); mmah(acc[1], af, bf + 2);
    }
    #pragma unroll
    for (int ni = 0; ni < 2; ni++) {
        const int ncol = wn * 16 + ni * 8 + 2 * c;
        const int r0 = wm * 16 + g;
        __half* dst = g_V + (size_t)(bm * 64 + r0) * 256 + bn * 64 + ncol;
        *(__half2*)dst           = *(__half2*)&acc[ni][0];
        *(__half2*)(dst + 8*256) = *(__half2*)&acc[ni][1];
    }
}

// ---------------- attn (f16, fused dot): stream others; softmax; abar ----------------
__global__ __launch_bounds__(256, 4)
void attn_kernel(const float* __restrict__ others) {
    extern __shared__ char sm[];
    __half* A  = (__half*)sm;              // [64][264] f16 (pad 8)
    float* alp = (float*)(sm + 34304);     // [64]
    const int t = threadIdx.x, w = t >> 5, lane = t & 31;
    const int b = blockIdx.x;

    uint4 vv = *(const uint4*)(g_V + (size_t)b * 256 + lane * 8);
    const __half2* vh = (const __half2*)&vv;
    float2 vf[4];
    #pragma unroll
    for (int i = 0; i < 4; i++) vf[i] = __half22float2(vh[i]);

    const float* src = others + (size_t)b * 16384;
    #pragma unroll
    for (int r = 0; r < 8; r++) {
        const int row = w * 8 + r;
        const float* p = src + row * 256 + lane * 8;
        float4 x0 = *(const float4*)p;
        float4 x1 = *(const float4*)(p + 4);
        float s = x0.x * vf[0].x + x0.y * vf[0].y + x0.z * vf[1].x + x0.w * vf[1].y
                + x1.x * vf[2].x + x1.y * vf[2].y + x1.z * vf[3].x + x1.w * vf[3].y;
        uint4 pk;
        ((__half2*)&pk)[0] = __floats2half2_rn(x0.x, x0.y);
        ((__half2*)&pk)[1] = __floats2half2_rn(x0.z, x0.w);
        ((__half2*)&pk)[2] = __floats2half2_rn(x1.x, x1.y);
        ((__half2*)&pk)[3] = __floats2half2_rn(x1.z, x1.w);
        *(uint4*)((char*)A + row * 528 + lane * 16) = pk;
        #pragma unroll
        for (int off = 16; off; off >>= 1) s += __shfl_xor_sync(~0u, s, off);
        if (lane == 0) alp[row] = s * 0.04419417382415922f;
    }
    __syncthreads();
    if (w == 0) {  // softmax over 64
        float a0 = alp[lane], a1 = alp[lane + 32];
        float m = fmaxf(a0, a1);
        #pragma unroll
        for (int off = 16; off; off >>= 1) m = fmaxf(m, __shfl_xor_sync(~0u, m, off));
        float e0 = __expf(a0 - m), e1 = __expf(a1 - m);
        float s = e0 + e1;
        #pragma unroll
        for (int off = 16; off; off >>= 1) s += __shfl_xor_sync(~0u, s, off);
        float inv = 1.0f / s;
        alp[lane] = e0 * inv; alp[lane + 32] = e1 * inv;
    }
    __syncthreads();
    float acc = 0.f;
    #pragma unroll 16
    for (int n = 0; n < 64; n++)
        acc = fmaf(alp[n], __half2float(A[n * 264 + t]), acc);
    g_Ab[(size_t)b * 256 + t] = __float2half(acc);
}

// ---------------- gemm3: C = Abar@W1 + b1; logits=[X,C]@W2 + b2; softmax+mask ----------------
// grid 128: 32 batch rows each.
__global__ __launch_bounds__(512, 1)
void gemm3(const float* __restrict__ b1g, const float* __restrict__ b2g,
           const int* __restrict__ action_mask, float* __restrict__ out) {
    extern __shared__ char sm[];
    const uint32_t sb = smem_u32(sm);
    char* Xt = sm;              // 32 x 64u (32K)
    char* Ct = sm + 32768;      // 32 x 64u (32K)
    char* At = sm + 65536;      // 32 x 32u (16K)
    char* Bb = sm + 81920;      // 128 x 32u (64K)
    __half* b1s = (__half*)(sm + 147456);
    __half* b2s = (__half*)(sm + 148480);
    float*  ls  = (float*)(sm + 148736);   // [32][132]
    const int t = threadIdx.x, w = t >> 5, lane = t & 31;
    const int bm = blockIdx.x;

    ld_tile(Xt, g_X  + (size_t)(bm * 32) * 512, 32, 64, 512, t, 512);
    ld_tile(At, g_Ab + (size_t)(bm * 32) * 256, 32, 32, 256, t, 512);
    b1s[t & 511] = __float2half(b1g[t & 511]);
    if (t < 128) b2s[t] = __float2half(b2g[t]);

    const int wm = w & 1, wn = w >> 1;
    const int lrow = lane & 15, lkh = lane >> 4;
    const int mrow = wm * 16 + lrow;
    const int nb = wn * 16 + lrow;
    const int g = lane >> 2, c = lane & 3;

    // ---- phase 1: C = Abar @ W1 + b1, stored f16 swizzled into Ct ----
    for (int npass = 0; npass < 4; npass++) {
        __syncthreads();
        ld_tile(Bb, g_W1T + (size_t)(npass * 128) * 256, 128, 32, 256, t, 512);
        __syncthreads();
        uint32_t acc[2][2] = {};
        #pragma unroll
        for (int ks = 0; ks < 16; ks++) {
            const int u = ks * 2 + lkh;
            uint32_t af[4], bf[4];
            ldsm4(af, sb + 65536u + (uint32_t)(mrow * 512) + sw_up(u, mrow) * 16);
            ldsm4(bf, sb + 81920u + (uint32_t)(nb * 512) + sw_up(u, nb) * 16);
            mmah(acc[0], af, bf); mmah(acc[1], af, bf + 2);
        }
        #pragma unroll
        for (int ni = 0; ni < 2; ni++) {
            const int ncolG = npass * 128 + wn * 16 + ni * 8 + 2 * c;
            const __half2 bias = *(__half2*)&b1s[ncolG];
            const int u = ncolG >> 3, ob = (ncolG & 7) * 2;
            const int r0 = wm * 16 + g;
            *(__half2*)(Ct + r0 * 1024 + sw_up(u, r0) * 16 + ob) =
                __hadd2(*(__half2*)&acc[ni][0], bias);
            *(__half2*)(Ct + (r0 + 8) * 1024 + sw_up(u, r0 + 8) * 16 + ob) =
                __hadd2(*(__half2*)&acc[ni][1], bias);
        }
    }

    // ---- phase 2: logits[32][128] = [X,C] @ W2 (K=1024 in 4 chunks) ----
    uint32_t acc[2][2] = {};
    for (int kc = 0; kc < 4; kc++) {
        __syncthreads();
        ld_tile(Bb, g_W2T + kc * 256, 128, 32, 1024, t, 512);
        __syncthreads();
        const uint32_t abase = sb + ((kc < 2) ? 0u : 32768u);
        const int uoff = (kc & 1) * 32;
        #pragma unroll
        for (int ks = 0; ks < 16; ks++) {
            const int u = uoff + ks * 2 + lkh;
            const int u2 = ks * 2 + lkh;
            uint32_t af[4], bf[4];
            ldsm4(af, abase + (uint32_t)(mrow * 1024) + sw_up(u, mrow) * 16);
            ldsm4(bf, sb + 81920u + (uint32_t)(nb * 512) + sw_up(u2, nb) * 16);
            mmah(acc[0], af, bf); mmah(acc[1], af, bf + 2);
        }
    }
    #pragma unroll
    for (int ni = 0; ni < 2; ni++) {
        const int col = wn * 16 + ni * 8 + 2 * c;
        float2 b2v = __half22float2(*(__half2*)&b2s[col]);
        const int r0 = wm * 16 + g;
        float2 v0 = __half22float2(*(__half2*)&acc[ni][0]);
        float2 v1 = __half22float2(*(__half2*)&acc[ni][1]);
        ls[r0 * 132 + col]           = v0.x + b2v.x;
        ls[r0 * 132 + col + 1]       = v0.y + b2v.y;
        ls[(r0 + 8) * 132 + col]     = v1.x + b2v.x;
        ls[(r0 + 8) * 132 + col + 1] = v1.y + b2v.y;
    }
    __syncthreads();

    // ---- softmax(128) + mask + write: warp w handles rows 2w, 2w+1 ----
    #pragma unroll
    for (int rr = 0; rr < 2; rr++) {
        const int row = w * 2 + rr;
        float v0 = ls[row * 132 + lane],      v1 = ls[row * 132 + lane + 32];
        float v2 = ls[row * 132 + lane + 64], v3 = ls[row * 132 + lane + 96];
        float m = fmaxf(fmaxf(v0, v1), fmaxf(v2, v3));
        #pragma unroll
        for (int off = 16; off; off >>= 1) m = fmaxf(m, __shfl_xor_sync(~0u, m, off));
        float e0 = __expf(v0 - m), e1 = __expf(v1 - m);
        float e2 = __expf(v2 - m), e3 = __expf(v3 - m);
        float s = e0 + e1 + e2 + e3;
        #pragma unroll
        for (int off = 16; off; off >>= 1) s += __shfl_xor_sync(~0u, s, off);
        const float inv = 1.0f / s;
        const size_t gb = (size_t)(bm * 32 + row);
        const int* mk = action_mask + gb * 128;
        float* op = out + gb * 128;
        op[lane]      = e0 * inv + NEGC * (1.0f - (float)mk[lane]);
        op[lane + 32] = e1 * inv + NEGC * (1.0f - (float)mk[lane + 32]);
        op[lane + 64] = e2 * inv + NEGC * (1.0f - (float)mk[lane + 64]);
        op[lane + 96] = e3 * inv + NEGC * (1.0f - (float)mk[lane + 96]);
    }
}

extern "C" void kernel_launch(void* const* d_in, const int* in_sizes, int n_in,
                              void* d_out, int out_size)
{
    const float* obs_x       = (const float*)d_in[0];
    const float* others      = (const float*)d_in[1];
    const int*   action_mask = (const int*)  d_in[2];
    const float* W1          = (const float*)d_in[3];
    const float* b1          = (const float*)d_in[4];
    const float* W2          = (const float*)d_in[5];
    const float* b2          = (const float*)d_in[6];
    // d_in[7..10] = W3,b3,W4,b4: dead in reference forward(), unused.

    cudaFuncSetAttribute(gemm1,       cudaFuncAttributeMaxDynamicSharedMemorySize, 98816);
    cudaFuncSetAttribute(gemm2,       cudaFuncAttributeMaxDynamicSharedMemorySize, 131072);
    cudaFuncSetAttribute(attn_kernel, cudaFuncAttributeMaxDynamicSharedMemorySize, 34816);
    cudaFuncSetAttribute(gemm3,       cudaFuncAttributeMaxDynamicSharedMemorySize, 165632);

    prep1<<<256, 256>>>(W1, W2, obs_x, b1, b2);
    gemm1<<<256, 512, 98816>>>(obs_x, b1);
    gemm2<<<256, 512, 131072>>>();
    attn_kernel<<<4096, 256, 34816>>>(others);
    gemm3<<<128, 512, 165632>>>(b1, b2, action_mask, (float*)d_out);
}